// round 5
// baseline (speedup 1.0000x reference)
#include <cuda_runtime.h>
#include <math.h>

#define B     4096
#define NN    2048
#define NIN   512
#define NEV   1536
#define NOUT  256
#define TT    128
#define NSTG  12
#define BM    32
#define BK    32

// Column-major activations: g_act[node * B + batch]. 32 MB static scratch.
__device__ float g_act[NN * (size_t)B];

// shared memory layout (bytes)
#define OFF_WD   0                        // float [128][129]   diag W block
#define OFF_WS2  66048                    // float2[32][129]    GEMM W tile, duplicated pairs
#define OFF_AS   (66048 + 33024)          // float [32][34]     GEMM A tile
#define OFF_ZS   (OFF_AS + 4352)          // float [128][33]    z / o staging
#define SMEM_TOTAL (OFF_ZS + 128*33*4)    // 120320 bytes

typedef unsigned long long u64;

__device__ __forceinline__ void fma2(u64 &c, u64 a, u64 w) {
    // packed 2-wide fp32 FMA (full-rate on sm_103a; plain FFMA reg-form is half-rate)
    asm("fma.rn.f32x2 %0, %1, %2, %0;" : "+l"(c) : "l"(a), "l"(w));
}

__global__ void __launch_bounds__(256, 1)
net_kernel(const float* __restrict__ W, const float* __restrict__ bias) {
    extern __shared__ char smem[];
    float*  Wd  = (float*) (smem + OFF_WD);
    float2* Ws2 = (float2*)(smem + OFF_WS2);
    float*  As  = (float*) (smem + OFF_AS);
    float*  Zs  = (float*) (smem + OFF_ZS);

    const int tid   = threadIdx.x;
    const int bbase = blockIdx.x * BM;
    const int tx    = tid & 31;   // node group within tile
    const int ty    = tid >> 5;   // batch group (0..7) -> 4 rows each

    for (int st = 0; st < NSTG; ++st) {
        const int node0 = st * TT;          // eval-row base in W (0-based)
        const int K     = NIN + node0;      // history length for this stage
        const int nch   = K >> 5;           // K / 32 chunks

        // ---- load the 128x128 strictly-lower diagonal W block (used by recurrence) ----
        for (int idx = tid; idx < TT * TT; idx += 256) {
            int t = idx >> 7, s = idx & 127;
            Wd[t * 129 + s] = W[(size_t)(node0 + t) * NN + (NIN + node0 + s)];
        }

        // ---- GEMM: Z[32 batch][128 nodes] = Act[:,0:K] @ Wblk^T ----
        u64 acc[4][2];
        #pragma unroll
        for (int i = 0; i < 4; i++) { acc[i][0] = 0ull; acc[i][1] = 0ull; }

        float pa[4]; float pw[16];
        {   // prefetch chunk 0 into registers
            const int b = tid & 31, kk = tid >> 5;
            #pragma unroll
            for (int ii = 0; ii < 4; ++ii)
                pa[ii] = g_act[(size_t)(kk + 8*ii) * B + bbase + b];
            const int k = tid & 31, tb = tid >> 5;
            #pragma unroll
            for (int jj = 0; jj < 16; ++jj)
                pw[jj] = W[(size_t)(node0 + tb + 8*jj) * NN + k];
        }

        for (int ch = 0; ch < nch; ++ch) {
            __syncthreads();
            {   // registers -> shared
                const int b = tid & 31, kk = tid >> 5;
                #pragma unroll
                for (int ii = 0; ii < 4; ++ii)
                    As[(kk + 8*ii) * 34 + b] = pa[ii];
                const int k = tid & 31, tb = tid >> 5;
                #pragma unroll
                for (int jj = 0; jj < 16; ++jj)
                    Ws2[k * 129 + tb + 8*jj] = make_float2(pw[jj], pw[jj]);
            }
            __syncthreads();
            if (ch + 1 < nch) {   // prefetch next chunk (LDGs overlap compute below)
                const int j0 = (ch + 1) << 5;
                const int b = tid & 31, kk = tid >> 5;
                #pragma unroll
                for (int ii = 0; ii < 4; ++ii)
                    pa[ii] = g_act[(size_t)(j0 + kk + 8*ii) * B + bbase + b];
                const int k = tid & 31, tb = tid >> 5;
                #pragma unroll
                for (int jj = 0; jj < 16; ++jj)
                    pw[jj] = W[(size_t)(node0 + tb + 8*jj) * NN + j0 + k];
            }
            #pragma unroll
            for (int kk2 = 0; kk2 < BK; ++kk2) {
                u64 a0 = *(const u64*)&As[kk2 * 34 + ty * 4];      // batch pair 0 (broadcast)
                u64 a1 = *(const u64*)&As[kk2 * 34 + ty * 4 + 2];  // batch pair 1
                #pragma unroll
                for (int i = 0; i < 4; i++) {
                    u64 w = *(const u64*)&Ws2[kk2 * 129 + tx + 32*i];
                    fma2(acc[i][0], a0, w);
                    fma2(acc[i][1], a1, w);
                }
            }
        }
        __syncthreads();

        // ---- stash z + bias into shared ----
        #pragma unroll
        for (int i = 0; i < 4; i++) {
            int t = tx + 32*i;
            float bi = __ldg(&bias[node0 + t]);
            float2 v0 = *(float2*)&acc[i][0];
            float2 v1 = *(float2*)&acc[i][1];
            Zs[t * 33 + ty*4 + 0] = v0.x + bi;
            Zs[t * 33 + ty*4 + 1] = v0.y + bi;
            Zs[t * 33 + ty*4 + 2] = v1.x + bi;
            Zs[t * 33 + ty*4 + 3] = v1.y + bi;
        }
        __syncthreads();

        // ---- triangular recurrence: 128 sequential sigmoid steps ----
        // warp = 4 batch rows; lane l: row r = l>>3, slot-group g = l&7,
        // owns z for nodes t = 8*i + g, i = 0..15, all in registers.
        {
            const int r  = tx >> 3;
            const int g  = tx & 7;
            const int bl = ty * 4 + r;
            float z[16];
            #pragma unroll
            for (int i = 0; i < 16; i++) z[i] = Zs[(8*i + g) * 33 + bl];

            #pragma unroll
            for (int s = 0; s < 128; ++s) {
                float zv = __shfl_sync(0xffffffffu, z[s >> 3], (r << 3) | (s & 7));
                float t5 = fminf(fmaxf(5.0f * zv, -60.0f), 60.0f);
                float o  = 1.0f / (1.0f + expf(-t5));
                if ((s & 7) == g) z[s >> 3] = o;   // owner keeps the output in place
                #pragma unroll
                for (int i = 0; i < 16; i++) {
                    int t = 8*i + g;
                    if (t > s) z[i] += Wd[t * 129 + s] * o;
                }
            }
            #pragma unroll
            for (int i = 0; i < 16; i++) Zs[(8*i + g) * 33 + bl] = z[i];  // now outputs o
        }
        __syncthreads();

        // ---- coalesced writeback of this stage's 128 output columns ----
        {
            const int b = tid & 31, t0 = tid >> 5;
            #pragma unroll
            for (int j = 0; j < 16; ++j) {
                int t = t0 + 8*j;
                g_act[(size_t)(NIN + node0 + t) * B + bbase + b] = Zs[t * 33 + b];
            }
        }
        // next-stage Wd writes are safe: all Wd reads finished before the
        // __syncthreads above; g_act writes become block-visible at the next
        // __syncthreads (chunk 0) before any chunk can read the new columns.
    }
}

// x [4096,512] row-major  ->  g_act[j*B + b]  (transpose via shared tile)
__global__ void init_kernel(const float* __restrict__ x) {
    __shared__ float tile[32][33];
    int j0 = blockIdx.x * 32;
    int b0 = blockIdx.y * 32;
    int tx = threadIdx.x & 31, ty = threadIdx.x >> 5;
    #pragma unroll
    for (int i = 0; i < 4; i++)
        tile[ty + 8*i][tx] = x[(size_t)(b0 + ty + 8*i) * NIN + j0 + tx];   // tile[b][j]
    __syncthreads();
    #pragma unroll
    for (int i = 0; i < 4; i++)
        g_act[(size_t)(j0 + ty + 8*i) * B + b0 + tx] = tile[tx][ty + 8*i];
}

// g_act last 256 columns -> d_out [4096,256] row-major
__global__ void out_kernel(float* __restrict__ out) {
    __shared__ float tile[32][33];
    int q0 = blockIdx.x * 32;
    int b0 = blockIdx.y * 32;
    int tx = threadIdx.x & 31, ty = threadIdx.x >> 5;
    #pragma unroll
    for (int i = 0; i < 4; i++)
        tile[ty + 8*i][tx] = g_act[(size_t)(NN - NOUT + q0 + ty + 8*i) * B + b0 + tx]; // tile[q][b]
    __syncthreads();
    #pragma unroll
    for (int i = 0; i < 4; i++)
        out[(size_t)(b0 + ty + 8*i) * NOUT + q0 + tx] = tile[tx][ty + 8*i];
}

extern "C" void kernel_launch(void* const* d_in, const int* in_sizes, int n_in,
                              void* d_out, int out_size) {
    const float* x = (const float*)d_in[0];   // [4096, 512]
    const float* W = (const float*)d_in[1];   // [1536, 2048]
    const float* b = (const float*)d_in[2];   // [1536]
    (void)in_sizes; (void)n_in; (void)out_size;

    cudaFuncSetAttribute(net_kernel, cudaFuncAttributeMaxDynamicSharedMemorySize, SMEM_TOTAL);

    init_kernel<<<dim3(NIN/32, B/32), 256>>>(x);
    net_kernel<<<B/BM, 256, SMEM_TOTAL>>>(W, b);
    out_kernel<<<dim3(NOUT/32, B/32), 256>>>((float*)d_out);
}

// round 8
// speedup vs baseline: 1.1889x; 1.1889x over previous
#include <cuda_runtime.h>
#include <math.h>

#define B     4096
#define NN    2048
#define NIN   512
#define NEV   1536
#define NOUT  256
#define TT    128
#define NSTG  12
#define BM    32
#define BK    32

// Column-major activations: g_act[node * B + batch]. 32 MB static scratch.
__device__ float g_act[NN * (size_t)B];

// shared memory layout (bytes)
#define OFF_WD   0                         // float [128][129]       diag W block
#define OFF_WS   66048                     // float2[32][64] swizzled node-pair W tile
#define OFF_AS   (66048 + 16384)           // float2[32][33]         duplicated (a,a) tile
#define OFF_ZS   (OFF_AS + 8448)           // float [128][33]        z / o staging
#define SMEM_TOTAL (OFF_ZS + 128*33*4)     // 107776 bytes

typedef unsigned long long u64;

__device__ __forceinline__ void fma2(u64 &c, u64 a, u64 w) {
    // packed 2-wide fp32 FMA (full-rate on sm_103a; plain FFMA reg-form is half-rate)
    asm("fma.rn.f32x2 %0, %1, %2, %0;" : "+l"(c) : "l"(a), "l"(w));
}

__global__ void __launch_bounds__(256, 1)
net_kernel(const float* __restrict__ W, const float* __restrict__ bias) {
    extern __shared__ char smem[];
    float*  Wd  = (float*) (smem + OFF_WD);
    float*  Wsf = (float*) (smem + OFF_WS);   // word-addressed swizzled pair store
    float2* As2 = (float2*)(smem + OFF_AS);   // (a,a) duplicated per batch
    float*  Zs  = (float*) (smem + OFF_ZS);

    const int tid   = threadIdx.x;
    const int bbase = blockIdx.x * BM;
    const int tx    = tid & 31;   // node-pair index within tile
    const int ty    = tid >> 5;   // batch group (0..7) -> 4 rows each

    for (int st = 0; st < NSTG; ++st) {
        const int node0 = st * TT;          // eval-row base in W (0-based)
        const int K     = NIN + node0;      // history length for this stage
        const int nch   = K >> 5;           // K / 32 chunks

        // ---- load the 128x128 strictly-lower diagonal W block (recurrence) ----
        for (int idx = tid; idx < TT * TT; idx += 256) {
            int t = idx >> 7, s = idx & 127;
            Wd[t * 129 + s] = W[(size_t)(node0 + t) * NN + (NIN + node0 + s)];
        }

        // ---- GEMM: Z[32 batch][128 nodes] = Act[:,0:K] @ Wblk^T ----
        // acc[i][j]: node pair (2*tx + 64*i, 2*tx+1 + 64*i), batch 4*ty + j
        u64 acc[2][4];
        #pragma unroll
        for (int i = 0; i < 2; i++)
            #pragma unroll
            for (int j = 0; j < 4; j++) acc[i][j] = 0ull;

        float pa[4]; float pw[16];
        {   // prefetch chunk 0 into registers (coalesced)
            const int b = tid & 31, kk = tid >> 5;
            #pragma unroll
            for (int ii = 0; ii < 4; ++ii)
                pa[ii] = g_act[(size_t)(kk + 8*ii) * B + bbase + b];
            const int k = tid & 31, tb = tid >> 5;
            #pragma unroll
            for (int jj = 0; jj < 16; ++jj)
                pw[jj] = W[(size_t)(node0 + tb + 8*jj) * NN + k];
        }

        for (int ch = 0; ch < nch; ++ch) {
            __syncthreads();
            {   // registers -> shared
                const int b = tid & 31, kk = tid >> 5;
                #pragma unroll
                for (int ii = 0; ii < 4; ++ii)
                    As2[(kk + 8*ii) * 33 + b] = make_float2(pa[ii], pa[ii]);
                const int k = tid & 31, tb = tid >> 5;
                #pragma unroll
                for (int jj = 0; jj < 16; ++jj) {
                    int n = tb + 8*jj;      // node 0..127
                    // swizzled node-pair layout: float2 idx = k*64 + ((n>>1) ^ (k&15))
                    Wsf[(k * 64 + ((n >> 1) ^ (k & 15))) * 2 + (n & 1)] = pw[jj];
                }
            }
            __syncthreads();
            if (ch + 1 < nch) {   // prefetch next chunk (LDGs overlap compute below)
                const int j0 = (ch + 1) << 5;
                const int b = tid & 31, kk = tid >> 5;
                #pragma unroll
                for (int ii = 0; ii < 4; ++ii)
                    pa[ii] = g_act[(size_t)(j0 + kk + 8*ii) * B + bbase + b];
                const int k = tid & 31, tb = tid >> 5;
                #pragma unroll
                for (int jj = 0; jj < 16; ++jj)
                    pw[jj] = W[(size_t)(node0 + tb + 8*jj) * NN + j0 + k];
            }
            #pragma unroll
            for (int kk2 = 0; kk2 < BK; ++kk2) {
                const int sw = (tx ^ (kk2 & 15));
                u64 w0 = *(const u64*)&Wsf[kk2 * 128 + 2*sw];        // nodes 2tx, 2tx+1
                u64 w1 = *(const u64*)&Wsf[kk2 * 128 + 2*sw + 64];   // nodes 2tx+64, 2tx+65
                #pragma unroll
                for (int j = 0; j < 4; ++j) {
                    u64 a = *(const u64*)&As2[kk2 * 33 + ty*4 + j];  // (a,a) broadcast
                    fma2(acc[0][j], a, w0);
                    fma2(acc[1][j], a, w1);
                }
            }
        }
        __syncthreads();

        // ---- stash z + bias into shared ----
        #pragma unroll
        for (int i = 0; i < 2; i++) {
            int t0 = 2*tx + 64*i;
            float b0 = __ldg(&bias[node0 + t0]);
            float b1 = __ldg(&bias[node0 + t0 + 1]);
            #pragma unroll
            for (int j = 0; j < 4; j++) {
                float2 v = *(float2*)&acc[i][j];
                int bl = ty*4 + j;
                Zs[ t0      * 33 + bl] = v.x + b0;
                Zs[(t0 + 1) * 33 + bl] = v.y + b1;
            }
        }
        __syncthreads();

        // ---- triangular recurrence: 128 sequential sigmoid steps ----
        // warp = 4 batch rows; lane l: row r = l>>3, slot-group g = l&7,
        // owns z for nodes t = 8*i + g, i = 0..15, all in registers.
        {
            const int r  = tx >> 3;
            const int g  = tx & 7;
            const int bl = ty * 4 + r;
            float z[16];
            #pragma unroll
            for (int i = 0; i < 16; i++) z[i] = Zs[(8*i + g) * 33 + bl];

            #pragma unroll
            for (int s = 0; s < 128; ++s) {
                float zv = __shfl_sync(0xffffffffu, z[s >> 3], (r << 3) | (s & 7));
                float t5 = fminf(fmaxf(5.0f * zv, -60.0f), 60.0f);
                float e  = __expf(-t5);                 // MUFU.EX2 path
                float o  = __fdividef(1.0f, 1.0f + e);  // MUFU.RCP path
                if ((s & 7) == g) z[s >> 3] = o;        // owner keeps output in place
                #pragma unroll
                for (int i = 0; i < 16; i++) {
                    int t = 8*i + g;
                    if (t > s) z[i] += Wd[t * 129 + s] * o;
                }
            }
            #pragma unroll
            for (int i = 0; i < 16; i++) Zs[(8*i + g) * 33 + bl] = z[i];  // now outputs o
        }
        __syncthreads();

        // ---- coalesced writeback of this stage's 128 output columns ----
        {
            const int b = tid & 31, t0 = tid >> 5;
            #pragma unroll
            for (int j = 0; j < 16; ++j) {
                int t = t0 + 8*j;
                g_act[(size_t)(NIN + node0 + t) * B + bbase + b] = Zs[t * 33 + b];
            }
        }
        // next-stage Wd writes are safe: all Wd reads finished before the
        // __syncthreads above; g_act writes become block-visible at the next
        // __syncthreads (chunk 0) before any chunk can read the new columns.
    }
}

// x [4096,512] row-major  ->  g_act[j*B + b]  (transpose via shared tile)
__global__ void init_kernel(const float* __restrict__ x) {
    __shared__ float tile[32][33];
    int j0 = blockIdx.x * 32;
    int b0 = blockIdx.y * 32;
    int tx = threadIdx.x & 31, ty = threadIdx.x >> 5;
    #pragma unroll
    for (int i = 0; i < 4; i++)
        tile[ty + 8*i][tx] = x[(size_t)(b0 + ty + 8*i) * NIN + j0 + tx];   // tile[b][j]
    __syncthreads();
    #pragma unroll
    for (int i = 0; i < 4; i++)
        g_act[(size_t)(j0 + ty + 8*i) * B + b0 + tx] = tile[tx][ty + 8*i];
}

// g_act last 256 columns -> d_out [4096,256] row-major
__global__ void out_kernel(float* __restrict__ out) {
    __shared__ float tile[32][33];
    int q0 = blockIdx.x * 32;
    int b0 = blockIdx.y * 32;
    int tx = threadIdx.x & 31, ty = threadIdx.x >> 5;
    #pragma unroll
    for (int i = 0; i < 4; i++)
        tile[ty + 8*i][tx] = g_act[(size_t)(NN - NOUT + q0 + ty + 8*i) * B + b0 + tx]; // tile[q][b]
    __syncthreads();
    #pragma unroll
    for (int i = 0; i < 4; i++)
        out[(size_t)(b0 + ty + 8*i) * NOUT + q0 + tx] = tile[tx][ty + 8*i];
}

extern "C" void kernel_launch(void* const* d_in, const int* in_sizes, int n_in,
                              void* d_out, int out_size) {
    const float* x = (const float*)d_in[0];   // [4096, 512]
    const float* W = (const float*)d_in[1];   // [1536, 2048]
    const float* b = (const float*)d_in[2];   // [1536]
    (void)in_sizes; (void)n_in; (void)out_size;

    cudaFuncSetAttribute(net_kernel, cudaFuncAttributeMaxDynamicSharedMemorySize, SMEM_TOTAL);

    init_kernel<<<dim3(NIN/32, B/32), 256>>>(x);
    net_kernel<<<B/BM, 256, SMEM_TOTAL>>>(W, b);
    out_kernel<<<dim3(NOUT/32, B/32), 256>>>((float*)d_out);
}